// round 6
// baseline (speedup 1.0000x reference)
#include <cuda_runtime.h>
#include <math.h>

#define NPTS    8192
#define KNN     16
#define KL      17               // 16 + self slot (self edge contributes 0)
#define G       32
#define G3      (G*G*G)          // 32768 cells per batch
#define BMAXF   6.0f             // P(|coord|>6) ~ 1e-4 over 98304 gaussians
#define IDXMASK 8191             // 13-bit index in mantissa LSBs
#define QTPB    128              // query block size

__device__ double   g_acc;
__device__ unsigned g_done;
__device__ int    g_cnt[4*G3];
__device__ int    g_cstart[4*(G3+1)];
__device__ int    g_cofs[4*G3];
__device__ int    g_cellid[4*NPTS];
__device__ float4 g_sref4[4*NPTS];    // sorted: (x,y,z,|p|^2/2)
__device__ float4 g_spred4[4*NPTS];

__device__ __forceinline__ int cell_of(float x, float y, float z) {
    const float inv_h = (float)G / (2.0f * BMAXF);
    int cx = (int)((x + BMAXF) * inv_h);
    int cy = (int)((y + BMAXF) * inv_h);
    int cz = (int)((z + BMAXF) * inv_h);
    cx = min(G-1, max(0, cx)); cy = min(G-1, max(0, cy)); cz = min(G-1, max(0, cz));
    return (cz * G + cy) * G + cx;
}

__global__ void k_zero(int ncells_total) {
    int i = blockIdx.x * blockDim.x + threadIdx.x;
    if (i == 0) { g_acc = 0.0; g_done = 0u; }
    if (i < ncells_total) g_cnt[i] = 0;
}

__global__ void k_hist(const float* __restrict__ pref, int total) {
    int i = blockIdx.x * blockDim.x + threadIdx.x;
    if (i >= total) return;
    int b = i / NPTS;
    int c = cell_of(pref[3*i], pref[3*i+1], pref[3*i+2]);
    g_cellid[i] = c;
    atomicAdd(&g_cnt[b * G3 + c], 1);
}

__global__ __launch_bounds__(1024) void k_scan() {   // grid = B blocks
    const int CH = G3 / 1024;                        // 32 cells per thread
    __shared__ int ps[1024];
    int b = blockIdx.x, t = threadIdx.x;
    int base = b * G3;
    int loc[CH];
    int s = 0;
#pragma unroll
    for (int u = 0; u < CH; u++) { loc[u] = s; s += g_cnt[base + t*CH + u]; }
    ps[t] = s;
    __syncthreads();
    for (int off = 1; off < 1024; off <<= 1) {
        int v = (t >= off) ? ps[t - off] : 0;
        __syncthreads();
        ps[t] += v;
        __syncthreads();
    }
    int excl = (t == 0) ? 0 : ps[t-1];
#pragma unroll
    for (int u = 0; u < CH; u++) {
        int c = t*CH + u;
        int st = excl + loc[u];
        g_cstart[b*(G3+1) + c] = st;
        g_cofs[base + c] = st;
    }
    if (t == 1023) g_cstart[b*(G3+1) + G3] = ps[1023];
}

__global__ void k_scatter(const float* __restrict__ pref,
                          const float* __restrict__ ppred, int total) {
    int i = blockIdx.x * blockDim.x + threadIdx.x;
    if (i >= total) return;
    int b = i / NPTS;
    int c = g_cellid[i];
    int pos = b * NPTS + atomicAdd(&g_cofs[b * G3 + c], 1);
    float x = pref[3*i], y = pref[3*i+1], z = pref[3*i+2];
    g_sref4[pos]  = make_float4(x, y, z, 0.5f*(x*x + y*y + z*z));
    g_spred4[pos] = make_float4(ppred[3*i], ppred[3*i+1], ppred[3*i+2], 0.0f);
}

__global__ __launch_bounds__(QTPB)
void k_query(float* __restrict__ out, float inv_total, int nblk_total) {
    __shared__ float warpsum[QTPB/32];
    const int tid = blockIdx.x * QTPB + threadIdx.x;
    const int b   = tid >> 13;           // /8192
    const int i   = tid & (NPTS-1);
    const int pbase = b * NPTS;
    const int cbase = b * (G3+1);

    const float4 q = g_sref4[pbase + i];
    const float xi = q.x, yi = q.y, zi = q.z, hq = q.w;
    const float inv_h = (float)G / (2.0f * BMAXF);
    const float h     = (2.0f * BMAXF) / (float)G;
    int cx = min(G-1, max(0, (int)((xi + BMAXF) * inv_h)));
    int cy = min(G-1, max(0, (int)((yi + BMAXF) * inv_h)));
    int cz = min(G-1, max(0, (int)((zi + BMAXF) * inv_h)));

    float val[KL];
#pragma unroll
    for (int k = 0; k < KL; k++) val[k] = __int_as_float(0x7F000000);
    float cmax = __int_as_float(0x7F000000);

    auto scan_cell = [&](int x, int y, int z) {
        int c  = (z * G + y) * G + x;
        int p0 = g_cstart[cbase + c];
        int p1 = g_cstart[cbase + c + 1];
        for (int p = p0; p < p1; p++) {
            float4 cc = g_sref4[pbase + p];
            float sc = fmaf(-cc.x, xi, fmaf(-cc.y, yi, fmaf(-cc.z, zi, cc.w + hq)));
            if (sc < cmax) {      // sc = d^2/2; self gives ~0, kept in list
                float cv = __int_as_float((__float_as_int(sc) & ~IDXMASK) | p);
#pragma unroll
                for (int k = 0; k < KL; k++) {
                    float lo = fminf(cv, val[k]);
                    float hi = fmaxf(cv, val[k]);
                    val[k] = lo; cv = hi;
                }
                cmax = val[KL-1];
            }
        }
    };

    for (int rho = 0; rho < G; rho++) {
        int x0 = max(cx - rho, 0), x1 = min(cx + rho, G-1);
        int y0 = max(cy - rho, 0), y1 = min(cy + rho, G-1);
        int z0 = max(cz - rho, 0), z1 = min(cz + rho, G-1);
        for (int z = z0; z <= z1; z++) {
            int dz = abs(z - cz);
            for (int y = y0; y <= y1; y++) {
                int dy = abs(y - cy);
                if (dz == rho || dy == rho) {
                    for (int x = x0; x <= x1; x++) scan_cell(x, y, z);
                } else {
                    if (cx - rho >= 0) scan_cell(cx - rho, y, z);
                    if (rho > 0 && cx + rho < G) scan_cell(cx + rho, y, z);
                }
            }
        }
        // exact stop: any unscanned point has d >= rho*h
        float gbnd = (float)rho * h;
        if (cmax * 2.004f <= gbnd * gbnd) break;          // margin for 13-bit quantization
        if (x0 == 0 && y0 == 0 && z0 == 0 && x1 == G-1 && y1 == G-1 && z1 == G-1) break;
    }

    // epilogue: exact edge lengths for the 17 kept entries (self -> 0)
    float s = 0.0f;
    const float4 qp = g_spred4[pbase + i];
#pragma unroll
    for (int k = 0; k < KL; k++) {
        int j = __float_as_int(val[k]) & IDXMASK;
        float4 rr = g_sref4[pbase + j];
        float4 pp = g_spred4[pbase + j];
        float dx = rr.x - xi, dy = rr.y - yi, dz = rr.z - zi;
        float dr = sqrtf(fmaf(dx, dx, fmaf(dy, dy, dz*dz)));
        float ex = pp.x - qp.x, ey = pp.y - qp.y, ez = pp.z - qp.z;
        float dp = sqrtf(fmaf(ex, ex, fmaf(ey, ey, ez*ez)));
        s += fabsf(dr - dp);
    }

#pragma unroll
    for (int o = 16; o > 0; o >>= 1)
        s += __shfl_down_sync(0xFFFFFFFFu, s, o);
    if ((threadIdx.x & 31) == 0) warpsum[threadIdx.x >> 5] = s;
    __syncthreads();

    if (threadIdx.x == 0) {
        float tt = 0.0f;
#pragma unroll
        for (int w = 0; w < QTPB/32; w++) tt += warpsum[w];
        atomicAdd(&g_acc, (double)tt);
        __threadfence();
        unsigned old = atomicAdd(&g_done, 1u);
        if (old == (unsigned)(nblk_total - 1)) {
            double total = atomicAdd(&g_acc, 0.0);
            out[0] = (float)total * inv_total;
        }
    }
}

extern "C" void kernel_launch(void* const* d_in, const int* in_sizes, int n_in,
                              void* d_out, int out_size) {
    const float* points_ref = (const float*)d_in[0];
    const float* points     = (const float*)d_in[1];
    float* out = (float*)d_out;

    const int B = in_sizes[0] / (NPTS * 3);               // 4
    const int total_pts = B * NPTS;
    const int ncells = B * G3;
    const float inv_total = 1.0f / (float)(B * NPTS * KNN);
    const int qblocks = total_pts / QTPB;                 // 256

    k_zero<<<(ncells + 255) / 256, 256>>>(ncells);
    k_hist<<<(total_pts + 255) / 256, 256>>>(points_ref, total_pts);
    k_scan<<<B, 1024>>>();
    k_scatter<<<(total_pts + 255) / 256, 256>>>(points_ref, points, total_pts);
    k_query<<<qblocks, QTPB>>>(out, inv_total, qblocks);
}

// round 7
// speedup vs baseline: 1.5493x; 1.5493x over previous
#include <cuda_runtime.h>
#include <math.h>

#define NPTS    8192
#define KNN     16
#define KL      17               // 16 + self slot (self edge contributes 0)
#define G       32
#define G3      (G*G*G)
#define BMAXF   6.0f
#define QTPB    256
#define WPB     (QTPB/32)        // 8 queries per block
#define FULLM   0xFFFFFFFFu

__device__ double   g_acc;
__device__ unsigned g_done;
__device__ int    g_cnt[4*G3];
__device__ int    g_cstart[4*(G3+1)];
__device__ int    g_cofs[4*G3];
__device__ int    g_cellid[4*NPTS];
__device__ float4 g_sref4[4*NPTS];    // counting-sorted: (x,y,z,|p|^2/2)
__device__ float4 g_spred4[4*NPTS];

__device__ __forceinline__ int cell_of(float x, float y, float z) {
    const float inv_h = (float)G / (2.0f * BMAXF);
    int cx = (int)((x + BMAXF) * inv_h);
    int cy = (int)((y + BMAXF) * inv_h);
    int cz = (int)((z + BMAXF) * inv_h);
    cx = min(G-1, max(0, cx)); cy = min(G-1, max(0, cy)); cz = min(G-1, max(0, cz));
    return (cz * G + cy) * G + cx;
}

__global__ void k_zero(int ncells_total) {
    int i = blockIdx.x * blockDim.x + threadIdx.x;
    if (i == 0) { g_acc = 0.0; g_done = 0u; }
    if (i < ncells_total) g_cnt[i] = 0;
}

__global__ void k_hist(const float* __restrict__ pref, int total) {
    int i = blockIdx.x * blockDim.x + threadIdx.x;
    if (i >= total) return;
    int b = i / NPTS;
    int c = cell_of(pref[3*i], pref[3*i+1], pref[3*i+2]);
    g_cellid[i] = c;
    atomicAdd(&g_cnt[b * G3 + c], 1);
}

__global__ __launch_bounds__(1024) void k_scan() {   // grid = B blocks
    const int CH = G3 / 1024;
    __shared__ int ps[1024];
    int b = blockIdx.x, t = threadIdx.x;
    int base = b * G3;
    int loc[CH];
    int s = 0;
#pragma unroll
    for (int u = 0; u < CH; u++) { loc[u] = s; s += g_cnt[base + t*CH + u]; }
    ps[t] = s;
    __syncthreads();
    for (int off = 1; off < 1024; off <<= 1) {
        int v = (t >= off) ? ps[t - off] : 0;
        __syncthreads();
        ps[t] += v;
        __syncthreads();
    }
    int excl = (t == 0) ? 0 : ps[t-1];
#pragma unroll
    for (int u = 0; u < CH; u++) {
        int c = t*CH + u;
        int st = excl + loc[u];
        g_cstart[b*(G3+1) + c] = st;
        g_cofs[base + c] = st;
    }
    if (t == 1023) g_cstart[b*(G3+1) + G3] = ps[1023];
}

__global__ void k_scatter(const float* __restrict__ pref,
                          const float* __restrict__ ppred, int total) {
    int i = blockIdx.x * blockDim.x + threadIdx.x;
    if (i >= total) return;
    int b = i / NPTS;
    int c = g_cellid[i];
    int pos = b * NPTS + atomicAdd(&g_cofs[b * G3 + c], 1);
    float x = pref[3*i], y = pref[3*i+1], z = pref[3*i+2];
    g_sref4[pos]  = make_float4(x, y, z, 0.5f*(x*x + y*y + z*z));
    g_spred4[pos] = make_float4(ppred[3*i], ppred[3*i+1], ppred[3*i+2], 0.0f);
}

// ------------------- one warp per query -------------------
__global__ __launch_bounds__(QTPB)
void k_query(float* __restrict__ out, float inv_total, int nblk_total) {
    __shared__ float wsum[WPB];
    const int lane = threadIdx.x & 31;
    const int w    = threadIdx.x >> 5;
    const int qw   = blockIdx.x * WPB + w;         // global query id
    const int b    = qw >> 13;
    const int i    = qw & (NPTS - 1);              // index in sorted array
    const int pbase = b * NPTS;
    const int cbase = b * (G3 + 1);

    const float4 q = g_sref4[pbase + i];
    const float xi = q.x, yi = q.y, zi = q.z, hq = q.w;
    const float inv_h = (float)G / (2.0f * BMAXF);
    const float h     = (2.0f * BMAXF) / (float)G;
    const int cx = min(G-1, max(0, (int)((xi + BMAXF) * inv_h)));
    const int cy = min(G-1, max(0, (int)((yi + BMAXF) * inv_h)));
    const int cz = min(G-1, max(0, (int)((zi + BMAXF) * inv_h)));

    const float INF = __int_as_float(0x7F800000);
    // distributed sorted top-KL: lane k holds the k-th smallest (score, idx)
    float myval = INF;
    int   myidx = i;
    float cmax  = INF;

    auto scan_seg = [&](int p0, int p1) {
        for (int pb = p0; pb < p1; pb += 32) {
            int p = pb + lane;
            float sc = INF;
            if (p < p1) {
                float4 c = g_sref4[pbase + p];
                sc = fmaf(-c.x, xi, fmaf(-c.y, yi, fmaf(-c.z, zi, c.w + hq)));
            }
            unsigned m = __ballot_sync(FULLM, sc < cmax);
            while (m) {
                int src = __ffs(m) - 1;
                m &= m - 1;
                float v = __shfl_sync(FULLM, sc, src);
                if (v < cmax) {
                    int id = pb + src;
                    float pv = __shfl_up_sync(FULLM, myval, 1);
                    int   pi = __shfl_up_sync(FULLM, myidx, 1);
                    if (lane == 0) pv = -INF;
                    if (v <= pv)        { myval = pv; myidx = pi; }
                    else if (v < myval) { myval = v;  myidx = id; }
                    cmax = __shfl_sync(FULLM, myval, KL - 1);
                }
            }
        }
    };
    auto scan_row = [&](int y, int z, int xa, int xb) {
        int c0 = (z * G + y) * G + xa;           // x-cells are contiguous
        int p0 = g_cstart[cbase + c0];
        int p1 = g_cstart[cbase + c0 + (xb - xa) + 1];
        scan_seg(p0, p1);
    };

    for (int rho = 0; ; rho++) {
        int x0 = max(cx - rho, 0), x1 = min(cx + rho, G-1);
        int y0 = max(cy - rho, 0), y1 = min(cy + rho, G-1);
        int z0 = max(cz - rho, 0), z1 = min(cz + rho, G-1);
        if (rho == 0) {
            scan_row(cy, cz, cx, cx);
        } else {
            for (int z = z0; z <= z1; z++) {
                int dz = abs(z - cz);
                for (int y = y0; y <= y1; y++) {
                    int dy = abs(y - cy);
                    if (dz == rho || dy == rho) {
                        scan_row(y, z, x0, x1);
                    } else {
                        if (cx - rho >= 0) scan_row(y, z, cx - rho, cx - rho);
                        if (cx + rho < G)  scan_row(y, z, cx + rho, cx + rho);
                    }
                }
            }
        }
        bool full = (x0 == 0 && y0 == 0 && z0 == 0 &&
                     x1 == G-1 && y1 == G-1 && z1 == G-1);
        if (full) break;
        float gb = (float)rho * h;                // unscanned points: d >= rho*h
        if (2.0f * cmax + 1e-4f <= gb * gb) break;
    }

    // epilogue: lane k computes its edge exactly; self entry -> |0-0| = 0
    float s = 0.0f;
    const float4 qp = g_spred4[pbase + i];
    if (lane < KL) {
        int j = myidx;
        float4 rr = g_sref4[pbase + j];
        float4 pp = g_spred4[pbase + j];
        float dx = rr.x - xi, dy = rr.y - yi, dz = rr.z - zi;
        float dr = sqrtf(fmaf(dx, dx, fmaf(dy, dy, dz*dz)));
        float ex = pp.x - qp.x, ey = pp.y - qp.y, ez = pp.z - qp.z;
        float dp = sqrtf(fmaf(ex, ex, fmaf(ey, ey, ez*ez)));
        s = fabsf(dr - dp);
    }
#pragma unroll
    for (int o = 16; o > 0; o >>= 1)
        s += __shfl_down_sync(FULLM, s, o);
    if (lane == 0) wsum[w] = s;
    __syncthreads();

    if (threadIdx.x == 0) {
        float tt = 0.0f;
#pragma unroll
        for (int u = 0; u < WPB; u++) tt += wsum[u];
        atomicAdd(&g_acc, (double)tt);
        __threadfence();
        unsigned old = atomicAdd(&g_done, 1u);
        if (old == (unsigned)(nblk_total - 1)) {
            double total = atomicAdd(&g_acc, 0.0);
            out[0] = (float)total * inv_total;
        }
    }
}

extern "C" void kernel_launch(void* const* d_in, const int* in_sizes, int n_in,
                              void* d_out, int out_size) {
    const float* points_ref = (const float*)d_in[0];
    const float* points     = (const float*)d_in[1];
    float* out = (float*)d_out;

    const int B = in_sizes[0] / (NPTS * 3);               // 4
    const int total_pts = B * NPTS;
    const int ncells = B * G3;
    const float inv_total = 1.0f / (float)(B * NPTS * KNN);
    const int qblocks = total_pts / WPB;                  // 4096 (1 warp/query)

    k_zero<<<(ncells + 255) / 256, 256>>>(ncells);
    k_hist<<<(total_pts + 255) / 256, 256>>>(points_ref, total_pts);
    k_scan<<<B, 1024>>>();
    k_scatter<<<(total_pts + 255) / 256, 256>>>(points_ref, points, total_pts);
    k_query<<<qblocks, QTPB>>>(out, inv_total, qblocks);
}

// round 8
// speedup vs baseline: 2.8423x; 1.8346x over previous
#include <cuda_runtime.h>
#include <math.h>

#define NPTS    8192
#define KNN     16
#define KL      17               // 16 + self slot (self edge contributes 0)
#define G       32
#define G3      (G*G*G)
#define BMAXF   6.0f
#define QTPB    256
#define WPB     (QTPB/32)        // 8 queries (warps) per block
#define FULLM   0xFFFFFFFFu

__device__ double   g_acc;
__device__ unsigned g_done;
__device__ int    g_cnt[4*G3];
__device__ int    g_cstart[4*(G3+1)];
__device__ int    g_cofs[4*G3];
__device__ int    g_cellid[4*NPTS];
__device__ float4 g_sref4[4*NPTS];    // counting-sorted: (x,y,z,|p|^2/2)
__device__ float4 g_spred4[4*NPTS];

__device__ __forceinline__ int cell_of(float x, float y, float z) {
    const float inv_h = (float)G / (2.0f * BMAXF);
    int cx = (int)((x + BMAXF) * inv_h);
    int cy = (int)((y + BMAXF) * inv_h);
    int cz = (int)((z + BMAXF) * inv_h);
    cx = min(G-1, max(0, cx)); cy = min(G-1, max(0, cy)); cz = min(G-1, max(0, cz));
    return (cz * G + cy) * G + cx;
}

__global__ void k_zero(int ncells_total) {
    int i = blockIdx.x * blockDim.x + threadIdx.x;
    if (i == 0) { g_acc = 0.0; g_done = 0u; }
    if (i < ncells_total) g_cnt[i] = 0;
}

__global__ void k_hist(const float* __restrict__ pref, int total) {
    int i = blockIdx.x * blockDim.x + threadIdx.x;
    if (i >= total) return;
    int b = i / NPTS;
    int c = cell_of(pref[3*i], pref[3*i+1], pref[3*i+2]);
    g_cellid[i] = c;
    atomicAdd(&g_cnt[b * G3 + c], 1);
}

__global__ __launch_bounds__(1024) void k_scan() {   // grid = B blocks
    const int CH = G3 / 1024;
    __shared__ int ps[1024];
    int b = blockIdx.x, t = threadIdx.x;
    int base = b * G3;
    int loc[CH];
    int s = 0;
#pragma unroll
    for (int u = 0; u < CH; u++) { loc[u] = s; s += g_cnt[base + t*CH + u]; }
    ps[t] = s;
    __syncthreads();
    for (int off = 1; off < 1024; off <<= 1) {
        int v = (t >= off) ? ps[t - off] : 0;
        __syncthreads();
        ps[t] += v;
        __syncthreads();
    }
    int excl = (t == 0) ? 0 : ps[t-1];
#pragma unroll
    for (int u = 0; u < CH; u++) {
        int c = t*CH + u;
        int st = excl + loc[u];
        g_cstart[b*(G3+1) + c] = st;
        g_cofs[base + c] = st;
    }
    if (t == 1023) g_cstart[b*(G3+1) + G3] = ps[1023];
}

__global__ void k_scatter(const float* __restrict__ pref,
                          const float* __restrict__ ppred, int total) {
    int i = blockIdx.x * blockDim.x + threadIdx.x;
    if (i >= total) return;
    int b = i / NPTS;
    int c = g_cellid[i];
    int pos = b * NPTS + atomicAdd(&g_cofs[b * G3 + c], 1);
    float x = pref[3*i], y = pref[3*i+1], z = pref[3*i+2];
    g_sref4[pos]  = make_float4(x, y, z, 0.5f*(x*x + y*y + z*z));
    g_spred4[pos] = make_float4(ppred[3*i], ppred[3*i+1], ppred[3*i+2], 0.0f);
}

// ---------------- one warp per query, flattened ring scan ----------------
__global__ __launch_bounds__(QTPB)
void k_query(float* __restrict__ out, float inv_total, int nblk_total) {
    __shared__ float wsum[WPB];
    const int lane = threadIdx.x & 31;
    const int w    = threadIdx.x >> 5;
    const int qw   = blockIdx.x * WPB + w;
    const int b    = qw >> 13;
    const int i    = qw & (NPTS - 1);          // index into sorted array
    const int pbase = b * NPTS;
    const int cbase = b * (G3 + 1);

    const float4 q = g_sref4[pbase + i];
    const float xi = q.x, yi = q.y, zi = q.z, hq = q.w;
    const float inv_h = (float)G / (2.0f * BMAXF);
    const float h     = (2.0f * BMAXF) / (float)G;
    const int cx = min(G-1, max(0, (int)((xi + BMAXF) * inv_h)));
    const int cy = min(G-1, max(0, (int)((yi + BMAXF) * inv_h)));
    const int cz = min(G-1, max(0, (int)((zi + BMAXF) * inv_h)));

    const float INF = __int_as_float(0x7F800000);
    // distributed sorted top-KL: lane k holds k-th smallest (score, idx)
    float myval = INF;
    int   myidx = i;
    float cmax  = INF;

    for (int rho = 0; ; rho++) {
        const int S = 2*rho + 1;
        const int sm2 = S - 2;
        const int n_rows = (rho == 0) ? 1 : 8*rho + 2*sm2*sm2;

        for (int rbase = 0; rbase < n_rows; rbase += 32) {
            const int r = rbase + lane;
            int p0 = 0, cnt = 0;
            if (r < n_rows) {
                int y, z, xa, xb;
                if (rho == 0) { y = cy; z = cz; xa = cx; xb = cx; }
                else if (r < S)        { z = cz - rho; y = cy - rho + r;            xa = cx-rho; xb = cx+rho; }
                else if (r < 2*S)      { z = cz + rho; y = cy - rho + (r - S);      xa = cx-rho; xb = cx+rho; }
                else if (r < 2*S+sm2)  { z = cz - rho + 1 + (r - 2*S); y = cy - rho; xa = cx-rho; xb = cx+rho; }
                else if (r < 2*S+2*sm2){ z = cz - rho + 1 + (r - 2*S - sm2); y = cy + rho; xa = cx-rho; xb = cx+rho; }
                else {
                    int idx2 = r - 8*rho;
                    int pair = idx2 >> 1;
                    int dyi = pair % sm2, dzi = pair / sm2;
                    y = cy - rho + 1 + dyi;
                    z = cz - rho + 1 + dzi;
                    int x = (idx2 & 1) ? cx + rho : cx - rho;
                    xa = x; xb = x;
                }
                xa = max(xa, 0); xb = min(xb, G-1);
                if (y >= 0 && y < G && z >= 0 && z < G && xa <= xb) {
                    int c0 = (z*G + y)*G + xa;
                    p0 = g_cstart[cbase + c0];
                    cnt = g_cstart[cbase + c0 + (xb - xa) + 1] - p0;
                }
            }
            // exclusive prefix scan of cnt across the warp
            int off = cnt;
#pragma unroll
            for (int d = 1; d < 32; d <<= 1) {
                int v = __shfl_up_sync(FULLM, off, d);
                if (lane >= d) off += v;
            }
            const int T = __shfl_sync(FULLM, off, 31);
            off -= cnt;                          // exclusive offset

            // flattened dense candidate scan: every lane works on a valid point
            for (int g0 = 0; g0 < T; g0 += 32) {
                const int g = g0 + lane;
                const int gq = min(g, T - 1);
                // binary search: largest row lo with off[lo] <= gq
                int lo = 0, hi = 31;
#pragma unroll
                for (int it = 0; it < 5; it++) {
                    int mid = (lo + hi + 1) >> 1;
                    int om = __shfl_sync(FULLM, off, mid);
                    if (om <= gq) lo = mid; else hi = mid - 1;
                }
                int offr = __shfl_sync(FULLM, off, lo);
                int p0r  = __shfl_sync(FULLM, p0,  lo);
                int p    = p0r + (gq - offr);

                float sc = INF;
                if (g < T) {
                    float4 c = g_sref4[pbase + p];
                    sc = fmaf(-c.x, xi, fmaf(-c.y, yi, fmaf(-c.z, zi, c.w + hq)));
                }
                // warp insert of accepted candidates into distributed list
                unsigned m = __ballot_sync(FULLM, sc < cmax);
                while (m) {
                    int src = __ffs(m) - 1;
                    m &= m - 1;
                    float v = __shfl_sync(FULLM, sc, src);
                    int  id = __shfl_sync(FULLM, p,  src);
                    if (v < cmax) {
                        float pv = __shfl_up_sync(FULLM, myval, 1);
                        int   pi = __shfl_up_sync(FULLM, myidx, 1);
                        if (lane == 0) pv = -INF;
                        if (v <= pv)        { myval = pv; myidx = pi; }
                        else if (v < myval) { myval = v;  myidx = id; }
                        cmax = __shfl_sync(FULLM, myval, KL - 1);
                    }
                }
            }
        }

        bool full = (cx - rho <= 0 && cx + rho >= G-1 &&
                     cy - rho <= 0 && cy + rho >= G-1 &&
                     cz - rho <= 0 && cz + rho >= G-1);
        if (full) break;
        float gb = (float)rho * h;               // unscanned points: d >= rho*h
        if (2.0f * cmax + 1e-4f <= gb * gb) break;
    }

    // epilogue: lane k computes its edge exactly; self entry -> |0-0| = 0
    float s = 0.0f;
    const float4 qp = g_spred4[pbase + i];
    if (lane < KL) {
        int j = myidx;
        float4 rr = g_sref4[pbase + j];
        float4 pp = g_spred4[pbase + j];
        float dx = rr.x - xi, dy = rr.y - yi, dz = rr.z - zi;
        float dr = sqrtf(fmaf(dx, dx, fmaf(dy, dy, dz*dz)));
        float ex = pp.x - qp.x, ey = pp.y - qp.y, ez = pp.z - qp.z;
        float dp = sqrtf(fmaf(ex, ex, fmaf(ey, ey, ez*ez)));
        s = fabsf(dr - dp);
    }
#pragma unroll
    for (int o = 16; o > 0; o >>= 1)
        s += __shfl_down_sync(FULLM, s, o);
    if (lane == 0) wsum[w] = s;
    __syncthreads();

    if (threadIdx.x == 0) {
        float tt = 0.0f;
#pragma unroll
        for (int u = 0; u < WPB; u++) tt += wsum[u];
        atomicAdd(&g_acc, (double)tt);
        __threadfence();
        unsigned old = atomicAdd(&g_done, 1u);
        if (old == (unsigned)(nblk_total - 1)) {
            double total = atomicAdd(&g_acc, 0.0);
            out[0] = (float)total * inv_total;
        }
    }
}

extern "C" void kernel_launch(void* const* d_in, const int* in_sizes, int n_in,
                              void* d_out, int out_size) {
    const float* points_ref = (const float*)d_in[0];
    const float* points     = (const float*)d_in[1];
    float* out = (float*)d_out;

    const int B = in_sizes[0] / (NPTS * 3);               // 4
    const int total_pts = B * NPTS;
    const int ncells = B * G3;
    const float inv_total = 1.0f / (float)(B * NPTS * KNN);
    const int qblocks = total_pts / WPB;                  // 4096

    k_zero<<<(ncells + 255) / 256, 256>>>(ncells);
    k_hist<<<(total_pts + 255) / 256, 256>>>(points_ref, total_pts);
    k_scan<<<B, 1024>>>();
    k_scatter<<<(total_pts + 255) / 256, 256>>>(points_ref, points, total_pts);
    k_query<<<qblocks, QTPB>>>(out, inv_total, qblocks);
}

// round 9
// speedup vs baseline: 3.0530x; 1.0741x over previous
#include <cuda_runtime.h>
#include <math.h>

#define NPTS    8192
#define KNN     16
#define KL      17               // 16 + self slot (self edge contributes 0)
#define G       32
#define G3      (G*G*G)
#define BMAXF   6.0f
#define QTPB    256
#define WPB     (QTPB/32)        // 8 queries (warps) per block
#define FULLM   0xFFFFFFFFu

__device__ double   g_acc;
__device__ unsigned g_done;
__device__ int    g_cnt[4*G3];
__device__ int    g_cstart[4*(G3+1)];
__device__ int    g_cofs[4*G3];
__device__ int    g_cellid[4*NPTS];
__device__ float4 g_sref4[4*NPTS];    // counting-sorted: (x,y,z,|p|^2/2)
__device__ float4 g_spred4[4*NPTS];

__device__ __forceinline__ int cell_of(float x, float y, float z) {
    const float inv_h = (float)G / (2.0f * BMAXF);
    int cx = (int)((x + BMAXF) * inv_h);
    int cy = (int)((y + BMAXF) * inv_h);
    int cz = (int)((z + BMAXF) * inv_h);
    cx = min(G-1, max(0, cx)); cy = min(G-1, max(0, cy)); cz = min(G-1, max(0, cz));
    return (cz * G + cy) * G + cx;
}

__global__ void k_zero(int ncells_total) {
    int i = blockIdx.x * blockDim.x + threadIdx.x;
    if (i == 0) { g_acc = 0.0; g_done = 0u; }
    if (i < ncells_total) g_cnt[i] = 0;
}

__global__ void k_hist(const float* __restrict__ pref, int total) {
    int i = blockIdx.x * blockDim.x + threadIdx.x;
    if (i >= total) return;
    int b = i / NPTS;
    int c = cell_of(pref[3*i], pref[3*i+1], pref[3*i+2]);
    g_cellid[i] = c;
    atomicAdd(&g_cnt[b * G3 + c], 1);
}

__global__ __launch_bounds__(1024) void k_scan() {   // grid = B blocks
    const int CH = G3 / 1024;
    __shared__ int ps[1024];
    int b = blockIdx.x, t = threadIdx.x;
    int base = b * G3;
    int loc[CH];
    int s = 0;
#pragma unroll
    for (int u = 0; u < CH; u++) { loc[u] = s; s += g_cnt[base + t*CH + u]; }
    ps[t] = s;
    __syncthreads();
    for (int off = 1; off < 1024; off <<= 1) {
        int v = (t >= off) ? ps[t - off] : 0;
        __syncthreads();
        ps[t] += v;
        __syncthreads();
    }
    int excl = (t == 0) ? 0 : ps[t-1];
#pragma unroll
    for (int u = 0; u < CH; u++) {
        int c = t*CH + u;
        int st = excl + loc[u];
        g_cstart[b*(G3+1) + c] = st;
        g_cofs[base + c] = st;
    }
    if (t == 1023) g_cstart[b*(G3+1) + G3] = ps[1023];
}

__global__ void k_scatter(const float* __restrict__ pref,
                          const float* __restrict__ ppred, int total) {
    int i = blockIdx.x * blockDim.x + threadIdx.x;
    if (i >= total) return;
    int b = i / NPTS;
    int c = g_cellid[i];
    int pos = b * NPTS + atomicAdd(&g_cofs[b * G3 + c], 1);
    float x = pref[3*i], y = pref[3*i+1], z = pref[3*i+2];
    g_sref4[pos]  = make_float4(x, y, z, 0.5f*(x*x + y*y + z*z));
    g_spred4[pos] = make_float4(ppred[3*i], ppred[3*i+1], ppred[3*i+2], 0.0f);
}

// ---------------- one warp per query, flattened ring scan ----------------
__global__ __launch_bounds__(QTPB)
void k_query(float* __restrict__ out, float inv_total, int nblk_total) {
    __shared__ float wsum[WPB];
    const int lane = threadIdx.x & 31;
    const int w    = threadIdx.x >> 5;
    const int qw   = blockIdx.x * WPB + w;
    const int b    = qw >> 13;
    const int i    = qw & (NPTS - 1);          // index into sorted array
    const int pbase = b * NPTS;
    const int cbase = b * (G3 + 1);

    const float4 q = g_sref4[pbase + i];
    const float xi = q.x, yi = q.y, zi = q.z, hq = q.w;
    const float inv_h = (float)G / (2.0f * BMAXF);
    const float h     = (2.0f * BMAXF) / (float)G;
    const int cx = min(G-1, max(0, (int)((xi + BMAXF) * inv_h)));
    const int cy = min(G-1, max(0, (int)((yi + BMAXF) * inv_h)));
    const int cz = min(G-1, max(0, (int)((zi + BMAXF) * inv_h)));

    const float INF = __int_as_float(0x7F800000);
    // distributed sorted lowest-32: lane k holds the k-th smallest (score,idx)
    float myval = INF;
    int   myidx = i;
    float cmax  = INF;

    for (int rho = 0; ; rho++) {
        const int S = 2*rho + 1;
        const int sm2 = S - 2;
        const int n_rows = (rho == 0) ? 1 : 8*rho + 2*sm2*sm2;

        for (int rbase = 0; rbase < n_rows; rbase += 32) {
            const int r = rbase + lane;
            int p0 = 0, cnt = 0;
            if (r < n_rows) {
                int y, z, xa, xb;
                if (rho == 0) { y = cy; z = cz; xa = cx; xb = cx; }
                else if (r < S)        { z = cz - rho; y = cy - rho + r;            xa = cx-rho; xb = cx+rho; }
                else if (r < 2*S)      { z = cz + rho; y = cy - rho + (r - S);      xa = cx-rho; xb = cx+rho; }
                else if (r < 2*S+sm2)  { z = cz - rho + 1 + (r - 2*S); y = cy - rho; xa = cx-rho; xb = cx+rho; }
                else if (r < 2*S+2*sm2){ z = cz - rho + 1 + (r - 2*S - sm2); y = cy + rho; xa = cx-rho; xb = cx+rho; }
                else {
                    int idx2 = r - 8*rho;
                    int pair = idx2 >> 1;
                    int dyi = pair % sm2, dzi = pair / sm2;
                    y = cy - rho + 1 + dyi;
                    z = cz - rho + 1 + dzi;
                    int x = (idx2 & 1) ? cx + rho : cx - rho;
                    xa = x; xb = x;
                }
                xa = max(xa, 0); xb = min(xb, G-1);
                if (y >= 0 && y < G && z >= 0 && z < G && xa <= xb) {
                    int c0 = (z*G + y)*G + xa;
                    p0 = g_cstart[cbase + c0];
                    cnt = g_cstart[cbase + c0 + (xb - xa) + 1] - p0;
                }
            }
            // exclusive prefix scan of cnt across the warp
            int off = cnt;
#pragma unroll
            for (int d = 1; d < 32; d <<= 1) {
                int v = __shfl_up_sync(FULLM, off, d);
                if (lane >= d) off += v;
            }
            const int T = __shfl_sync(FULLM, off, 31);
            off -= cnt;                          // exclusive offset

            // flattened dense candidate scan
            for (int g0 = 0; g0 < T; g0 += 32) {
                const int g = g0 + lane;
                const int gq = min(g, T - 1);
                int lo = 0, hi = 31;
#pragma unroll
                for (int it = 0; it < 5; it++) {
                    int mid = (lo + hi + 1) >> 1;
                    int om = __shfl_sync(FULLM, off, mid);
                    if (om <= gq) lo = mid; else hi = mid - 1;
                }
                int offr = __shfl_sync(FULLM, off, lo);
                int p0r  = __shfl_sync(FULLM, p0,  lo);
                int p    = p0r + (gq - offr);

                float sc = INF;
                if (g < T) {
                    float4 c = g_sref4[pbase + p];
                    sc = fmaf(-c.x, xi, fmaf(-c.y, yi, fmaf(-c.z, zi, c.w + hq)));
                }
                unsigned m = __ballot_sync(FULLM, sc < cmax);
                int nacc = __popc(m);
                if (nacc >= 10) {
                    // --- bitonic path: sort chunk, merge with resident list ---
                    float sv = sc; int si = p;
#pragma unroll
                    for (int k = 2; k <= 32; k <<= 1) {
#pragma unroll
                        for (int j = k >> 1; j > 0; j >>= 1) {
                            float ov = __shfl_xor_sync(FULLM, sv, j);
                            int   oi = __shfl_xor_sync(FULLM, si, j);
                            bool keep_min = ((lane & j) == 0) == ((lane & k) == 0);
                            bool take = keep_min ? (ov < sv) : (ov > sv);
                            if (take) { sv = ov; si = oi; }
                        }
                    }
                    // reverse chunk (desc), elementwise min with asc list -> bitonic lows
                    float rv = __shfl_sync(FULLM, sv, 31 - lane);
                    int   ri = __shfl_sync(FULLM, si, 31 - lane);
                    if (rv < myval) { myval = rv; myidx = ri; }
                    // bitonic cleanup of the lows (ascending)
#pragma unroll
                    for (int j = 16; j > 0; j >>= 1) {
                        float ov = __shfl_xor_sync(FULLM, myval, j);
                        int   oi = __shfl_xor_sync(FULLM, myidx, j);
                        bool keep_min = ((lane & j) == 0);
                        bool take = keep_min ? (ov < myval) : (ov > myval);
                        if (take) { myval = ov; myidx = oi; }
                    }
                    cmax = __shfl_sync(FULLM, myval, KL - 1);
                } else {
                    while (m) {
                        int src = __ffs(m) - 1;
                        m &= m - 1;
                        float v = __shfl_sync(FULLM, sc, src);
                        int  id = __shfl_sync(FULLM, p,  src);
                        if (v < cmax) {
                            float pv = __shfl_up_sync(FULLM, myval, 1);
                            int   pi = __shfl_up_sync(FULLM, myidx, 1);
                            if (lane == 0) pv = -INF;
                            if (v <= pv)        { myval = pv; myidx = pi; }
                            else if (v < myval) { myval = v;  myidx = id; }
                            cmax = __shfl_sync(FULLM, myval, KL - 1);
                        }
                    }
                }
            }
        }

        // exact stop: distance from query to the scanned-box boundary.
        // Sides clipped at the domain edge have no cells beyond -> +INF margin.
        float dmin = INF;
        if (cx - rho > 0)     dmin = fminf(dmin, xi - ((float)(cx - rho) * h - BMAXF));
        if (cx + rho < G - 1) dmin = fminf(dmin, ((float)(cx + rho + 1) * h - BMAXF) - xi);
        if (cy - rho > 0)     dmin = fminf(dmin, yi - ((float)(cy - rho) * h - BMAXF));
        if (cy + rho < G - 1) dmin = fminf(dmin, ((float)(cy + rho + 1) * h - BMAXF) - yi);
        if (cz - rho > 0)     dmin = fminf(dmin, zi - ((float)(cz - rho) * h - BMAXF));
        if (cz + rho < G - 1) dmin = fminf(dmin, ((float)(cz + rho + 1) * h - BMAXF) - zi);
        if (dmin == INF) break;                           // box covers whole grid
        if (2.0f * cmax + 1e-4f <= dmin * dmin) break;
    }

    // epilogue: lane k computes its edge exactly; self entry -> |0-0| = 0
    float s = 0.0f;
    const float4 qp = g_spred4[pbase + i];
    if (lane < KL) {
        int j = myidx;
        float4 rr = g_sref4[pbase + j];
        float4 pp = g_spred4[pbase + j];
        float dx = rr.x - xi, dy = rr.y - yi, dz = rr.z - zi;
        float dr = sqrtf(fmaf(dx, dx, fmaf(dy, dy, dz*dz)));
        float ex = pp.x - qp.x, ey = pp.y - qp.y, ez = pp.z - qp.z;
        float dp = sqrtf(fmaf(ex, ex, fmaf(ey, ey, ez*ez)));
        s = fabsf(dr - dp);
    }
#pragma unroll
    for (int o = 16; o > 0; o >>= 1)
        s += __shfl_down_sync(FULLM, s, o);
    if (lane == 0) wsum[w] = s;
    __syncthreads();

    if (threadIdx.x == 0) {
        float tt = 0.0f;
#pragma unroll
        for (int u = 0; u < WPB; u++) tt += wsum[u];
        atomicAdd(&g_acc, (double)tt);
        __threadfence();
        unsigned old = atomicAdd(&g_done, 1u);
        if (old == (unsigned)(nblk_total - 1)) {
            double total = atomicAdd(&g_acc, 0.0);
            out[0] = (float)total * inv_total;
        }
    }
}

extern "C" void kernel_launch(void* const* d_in, const int* in_sizes, int n_in,
                              void* d_out, int out_size) {
    const float* points_ref = (const float*)d_in[0];
    const float* points     = (const float*)d_in[1];
    float* out = (float*)d_out;

    const int B = in_sizes[0] / (NPTS * 3);               // 4
    const int total_pts = B * NPTS;
    const int ncells = B * G3;
    const float inv_total = 1.0f / (float)(B * NPTS * KNN);
    const int qblocks = total_pts / WPB;                  // 4096

    k_zero<<<(ncells + 255) / 256, 256>>>(ncells);
    k_hist<<<(total_pts + 255) / 256, 256>>>(points_ref, total_pts);
    k_scan<<<B, 1024>>>();
    k_scatter<<<(total_pts + 255) / 256, 256>>>(points_ref, points, total_pts);
    k_query<<<qblocks, QTPB>>>(out, inv_total, qblocks);
}